// round 2
// baseline (speedup 1.0000x reference)
#include <cuda_runtime.h>

// SimpleTTS decoder-only (encoder output unused, all batch rows identical,
// frame feedback folded into the hidden recurrence):
//   g_t = Wcomb @ h_{t-1} + bcomb,  Wcomb = dec_Whh + dec_Wih @ lin_W
// Persistent 128-CTA kernel (1/SM), weights register-resident (64 regs/thr),
// h exchanged via L2 with per-CTA release/acquire flags; poll+load fused.

#define HID   1024
#define GATES 4096
#define MEL   80
#define NCTA  128
#define JPC   8
#define NTHR  512
#define MAXT  1024
#define TT    8      // timesteps per finalize CTA

__device__ float        d_Wcomb[GATES * HID];   // 16.7 MB
__device__ float        d_bcomb[GATES];
__device__ float        d_b0[GATES];
__device__ float        d_hhist[MAXT * HID];
__device__ unsigned int d_flags[NCTA];

__device__ __forceinline__ float fast_sig(float x) {
    return __fdividef(1.0f, 1.0f + __expf(-x));
}
__device__ __forceinline__ float fast_tanh(float x) {
    x = fminf(fmaxf(x, -15.0f), 15.0f);
    float e = __expf(-2.0f * x);
    return __fdividef(1.0f - e, 1.0f + e);
}
__device__ __forceinline__ void fma2(unsigned long long& acc,
                                     unsigned long long a, unsigned long long b) {
    asm("fma.rn.f32x2 %0, %1, %2, %0;" : "+l"(acc) : "l"(a), "l"(b));
}
__device__ __forceinline__ float2 unpack2(unsigned long long v) {
    float2 r;
    asm("mov.b64 {%0,%1}, %2;" : "=f"(r.x), "=f"(r.y) : "l"(v));
    return r;
}

// ---------------------------------------------------------------------------
__global__ void prep_bias(const float* __restrict__ Wih,
                          const float* __restrict__ bih,
                          const float* __restrict__ bhh,
                          const float* __restrict__ linb) {
    int g = blockIdx.x * blockDim.x + threadIdx.x;
    if (g < GATES) {
        float s = bih[g] + bhh[g];
        d_b0[g] = s;
        float a = 0.0f;
        #pragma unroll 8
        for (int k = 0; k < MEL; ++k) a = fmaf(Wih[g * MEL + k], linb[k], a);
        d_bcomb[g] = s + a;
    }
    if (g < NCTA) d_flags[g] = 0;
}

// Wcomb = Whh + Wih @ lin_W
__global__ void prep_wcomb(const float* __restrict__ Wih,
                           const float* __restrict__ Whh,
                           const float* __restrict__ linW) {
    __shared__ float wih_s[16 * MEL];
    const int r0 = blockIdx.x * 16;
    for (int i = threadIdx.x; i < 16 * MEL; i += 256)
        wih_s[i] = Wih[r0 * MEL + i];
    __syncthreads();
    for (int c = threadIdx.x; c < HID; c += 256) {
        float acc[16];
        #pragma unroll
        for (int r = 0; r < 16; ++r) acc[r] = 0.0f;
        for (int k = 0; k < MEL; ++k) {
            float lw = __ldg(linW + (size_t)k * HID + c);
            #pragma unroll
            for (int r = 0; r < 16; ++r) acc[r] = fmaf(wih_s[r * MEL + k], lw, acc[r]);
        }
        #pragma unroll
        for (int r = 0; r < 16; ++r)
            d_Wcomb[(size_t)(r0 + r) * HID + c] =
                Whh[(size_t)(r0 + r) * HID + c] + acc[r];
    }
}

// ---------------------------------------------------------------------------
// Persistent recurrence. 512 thr/CTA, 16 warps x 64 columns.
// Lane l of every warp owns gate-row: gate = l>>3, jj = l&7,
//   grow = gate*HID + blockIdx.x*JPC + jj   (32 rows per CTA)
// Threads 0..127 fuse poll(flag[k]) + load(h slice k) into SMEM.
// Warp 0 finishes gates, updates c/h for this CTA's 8 h elements, publishes.
// ---------------------------------------------------------------------------
__global__ void __launch_bounds__(NTHR, 1) tts_main(int T) {
    __shared__ float h_s[HID];
    __shared__ float red_s[32 * 17];
    const int tid = threadIdx.x;
    const int w   = tid >> 5;
    const int l   = tid & 31;
    const int ct  = blockIdx.x;
    const int jj  = l & 7;
    const int grow = (l >> 3) * HID + ct * JPC + jj;

    // 64-float register slice packed as 32 f32x2 (64 regs/thread).
    unsigned long long W2[32];
    {
        const longlong2* wg =
            (const longlong2*)(d_Wcomb + (size_t)grow * HID + (w << 6));
        #pragma unroll
        for (int k = 0; k < 16; ++k) {
            longlong2 v = wg[k];
            W2[2 * k]     = (unsigned long long)v.x;
            W2[2 * k + 1] = (unsigned long long)v.y;
        }
    }
    const float bc = d_bcomb[grow];
    float c = 0.0f;

    // ---- step 0 (h = 0) ----
    if (w == 0) {
        float gv = d_b0[grow];
        float vi = __shfl_sync(0xffffffffu, gv, jj);
        float vg = __shfl_sync(0xffffffffu, gv, jj + 16);
        float vo = __shfl_sync(0xffffffffu, gv, jj + 24);
        if (l < 8) {
            c = fast_sig(vi) * fast_tanh(vg);
            float hh = fast_sig(vo) * fast_tanh(c);
            asm volatile("st.global.cg.f32 [%0], %1;"
                         :: "l"(d_hhist + ct * JPC + l), "f"(hh) : "memory");
        }
        __syncwarp();
        if (l == 0)
            asm volatile("st.release.gpu.global.u32 [%0], %1;"
                         :: "l"(d_flags + ct), "r"(1u) : "memory");
    }

    for (int t = 1; t < T; ++t) {
        // fused poll + per-slice h load (thread k owns CTA k's 8 floats)
        if (tid < NCTA) {
            unsigned v;
            do {
                asm volatile("ld.acquire.gpu.global.u32 %0, [%1];"
                             : "=r"(v) : "l"(d_flags + tid) : "memory");
            } while (v < (unsigned)t);
            const float4* src =
                (const float4*)(d_hhist + (size_t)(t - 1) * HID) + tid * 2;
            float4 a = __ldcg(src);
            float4 b = __ldcg(src + 1);
            ((float4*)h_s)[tid * 2]     = a;
            ((float4*)h_s)[tid * 2 + 1] = b;
        }
        __syncthreads();

        // packed 64-wide dot, h broadcast from SMEM
        unsigned long long a0 = 0ull, a1 = 0ull;
        const longlong2* h2 = (const longlong2*)(h_s + (w << 6));
        #pragma unroll
        for (int k = 0; k < 16; ++k) {
            longlong2 hv = h2[k];
            fma2(a0, W2[2 * k],     (unsigned long long)hv.x);
            fma2(a1, W2[2 * k + 1], (unsigned long long)hv.y);
        }
        float2 p0 = unpack2(a0), p1 = unpack2(a1);
        red_s[l * 17 + w] = (p0.x + p0.y) + (p1.x + p1.y);
        __syncthreads();

        if (w == 0) {
            const float* rr = red_s + l * 17;
            float s0 = rr[0] + rr[1],   s1 = rr[2] + rr[3];
            float s2 = rr[4] + rr[5],   s3 = rr[6] + rr[7];
            float s4 = rr[8] + rr[9],   s5 = rr[10] + rr[11];
            float s6 = rr[12] + rr[13], s7 = rr[14] + rr[15];
            float gv = ((s0 + s1) + (s2 + s3)) + ((s4 + s5) + (s6 + s7)) + bc;
            float vi = __shfl_sync(0xffffffffu, gv, jj);
            float vf = __shfl_sync(0xffffffffu, gv, jj + 8);
            float vg = __shfl_sync(0xffffffffu, gv, jj + 16);
            float vo = __shfl_sync(0xffffffffu, gv, jj + 24);
            if (l < 8) {
                c = fast_sig(vf) * c + fast_sig(vi) * fast_tanh(vg);
                float hh = fast_sig(vo) * fast_tanh(c);
                asm volatile("st.global.cg.f32 [%0], %1;"
                             :: "l"(d_hhist + (size_t)t * HID + ct * JPC + l),
                                "f"(hh) : "memory");
            }
            __syncwarp();
            if (l == 0)
                asm volatile("st.release.gpu.global.u32 [%0], %1;"
                             :: "l"(d_flags + ct), "r"((unsigned)(t + 1)) : "memory");
        }
    }
}

// ---------------------------------------------------------------------------
// frames[t] = lin_W @ h_t + lin_b, 8 timesteps per CTA, broadcast over batch.
// ---------------------------------------------------------------------------
__global__ void __launch_bounds__(NTHR) finalize(const float* __restrict__ linW,
                                                 const float* __restrict__ linb,
                                                 float* __restrict__ out,
                                                 int T, int B) {
    __shared__ float h_s[TT][HID];
    __shared__ float fr[TT][MEL];
    const int t0  = blockIdx.x * TT;
    const int tid = threadIdx.x;
    const int w   = tid >> 5, l = tid & 31;

    for (int i = tid; i < TT * HID / 4; i += NTHR)
        ((float4*)h_s)[i] = ((const float4*)(d_hhist + (size_t)t0 * HID))[i];
    __syncthreads();

    for (int m = w; m < MEL; m += 16) {
        const float* wrow = linW + (size_t)m * HID;
        float s[TT];
        #pragma unroll
        for (int j = 0; j < TT; ++j) s[j] = 0.0f;
        for (int k = l; k < HID; k += 32) {
            float wv = wrow[k];
            #pragma unroll
            for (int j = 0; j < TT; ++j) s[j] = fmaf(wv, h_s[j][k], s[j]);
        }
        #pragma unroll
        for (int j = 0; j < TT; ++j) {
            #pragma unroll
            for (int off = 16; off; off >>= 1)
                s[j] += __shfl_down_sync(0xffffffffu, s[j], off);
        }
        if (l == 0) {
            float bb = linb[m];
            #pragma unroll
            for (int j = 0; j < TT; ++j) fr[j][m] = s[j] + bb;
        }
    }
    __syncthreads();

    const int tot = B * TT * MEL;
    for (int i = tid; i < tot; i += NTHR) {
        int b = i / (TT * MEL);
        int r = i - b * (TT * MEL);
        int j = r / MEL;
        int m = r - j * MEL;
        int t = t0 + j;
        if (t < T) out[((size_t)b * T + t) * MEL + m] = fr[j][m];
    }
}

// ---------------------------------------------------------------------------
extern "C" void kernel_launch(void* const* d_in, const int* in_sizes, int n_in,
                              void* d_out, int out_size) {
    if (n_in < 6) return;
    const float* dec_Wih = (const float*)d_in[n_in - 6];
    const float* dec_Whh = (const float*)d_in[n_in - 5];
    const float* dec_bih = (const float*)d_in[n_in - 4];
    const float* dec_bhh = (const float*)d_in[n_in - 3];
    const float* lin_W   = (const float*)d_in[n_in - 2];
    const float* lin_b   = (const float*)d_in[n_in - 1];

    const int B = in_sizes[1];
    int T = out_size / (B * MEL);
    if (T > MAXT) T = MAXT;
    if (T <= 0) return;

    prep_bias <<<GATES / 256, 256>>>(dec_Wih, dec_bih, dec_bhh, lin_b);
    prep_wcomb<<<GATES / 16,  256>>>(dec_Wih, dec_Whh, lin_W);
    tts_main  <<<NCTA,        NTHR>>>(T);
    finalize  <<<(T + TT - 1) / TT, NTHR>>>(lin_W, lin_b, (float*)d_out, T, B);
}

// round 6
// speedup vs baseline: 2.8716x; 2.8716x over previous
#include <cuda_runtime.h>

// SimpleTTS decoder-only. Recurrence folded to h-only:
//   g_t = Wcomb @ h_{t-1} + bcomb,  Wcomb = dec_Whh + dec_Wih @ lin_W
// Persistent 128-CTA kernel, weights register-resident (128 regs/thread).
// Sync (R1-proven primitive): producers st.global.cg h -> __syncwarp ->
// lane0 st.release.gpu flag; consumers spin ld.acquire.gpu on the flag.
// NEW: flags padded to one 128B L2 line per CTA (kills LTS queueing of
// 16K pollers on 2 lines) + nanosleep backoff in the spin + fused
// poll+load. Finalize fused -> 2 launches per call.

#define HID   1024
#define GATES 4096
#define MEL   80
#define NCTA  128
#define JPC   8
#define NTHR  256
#define GRID  148      // pad grid past the low-grid throttle threshold
#define MAXT  1024
#define TT    8
#define FPAD  32       // flag stride in words (128B line)

__device__ float        d_Wcomb[GATES * HID];       // 16.7 MB
__device__ float        d_bcomb[GATES];
__device__ float        d_b0[GATES];
__device__ float        d_hhist[MAXT * HID];
__device__ unsigned int d_flags[NCTA * FPAD];       // one line per CTA

__device__ __forceinline__ float fast_sig(float x) {
    return __fdividef(1.0f, 1.0f + __expf(-x));
}
__device__ __forceinline__ float fast_tanh(float x) {
    x = fminf(fmaxf(x, -15.0f), 15.0f);
    float e = __expf(-2.0f * x);
    return __fdividef(1.0f - e, 1.0f + e);
}
__device__ __forceinline__ void fma2(unsigned long long& acc,
                                     unsigned long long a, unsigned long long b) {
    asm("fma.rn.f32x2 %0, %1, %2, %0;" : "+l"(acc) : "l"(a), "l"(b));
}
__device__ __forceinline__ float2 unpack2(unsigned long long v) {
    float2 r;
    asm("mov.b64 {%0,%1}, %2;" : "=f"(r.x), "=f"(r.y) : "l"(v));
    return r;
}
// Acquire-load spin (the only empirically-correct primitive on this part),
// with nanosleep backoff to keep LTS poll pressure negligible.
__device__ __forceinline__ void wait_flag_acq(const unsigned int* p, unsigned tgt) {
    unsigned v;
    asm volatile("ld.acquire.gpu.global.u32 %0, [%1];" : "=r"(v) : "l"(p) : "memory");
    while (v < tgt) {
        __nanosleep(64);
        asm volatile("ld.acquire.gpu.global.u32 %0, [%1];" : "=r"(v) : "l"(p) : "memory");
    }
}

// ---------------------------------------------------------------------------
// Prep: Wcomb = Whh + Wih @ lin_W, biases, flags reset.
// ---------------------------------------------------------------------------
__global__ void prep(const float* __restrict__ Wih,
                     const float* __restrict__ Whh,
                     const float* __restrict__ linW,
                     const float* __restrict__ bih,
                     const float* __restrict__ bhh,
                     const float* __restrict__ linb) {
    __shared__ float wih_s[16 * MEL];
    const int r0 = blockIdx.x * 16;
    for (int i = threadIdx.x; i < 16 * MEL; i += 256)
        wih_s[i] = Wih[r0 * MEL + i];
    __syncthreads();

    for (int c = threadIdx.x; c < HID; c += 256) {
        float acc[16];
        #pragma unroll
        for (int r = 0; r < 16; ++r) acc[r] = 0.0f;
        for (int k = 0; k < MEL; ++k) {
            float lw = __ldg(linW + (size_t)k * HID + c);
            #pragma unroll
            for (int r = 0; r < 16; ++r) acc[r] = fmaf(wih_s[r * MEL + k], lw, acc[r]);
        }
        #pragma unroll
        for (int r = 0; r < 16; ++r)
            d_Wcomb[(size_t)(r0 + r) * HID + c] =
                Whh[(size_t)(r0 + r) * HID + c] + acc[r];
    }

    if (threadIdx.x < 16) {
        int g = r0 + threadIdx.x;
        float s = bih[g] + bhh[g];
        d_b0[g] = s;
        float a = 0.0f;
        #pragma unroll 8
        for (int k = 0; k < MEL; ++k) a = fmaf(wih_s[threadIdx.x * MEL + k], linb[k], a);
        d_bcomb[g] = s + a;
    }
    // reset all padded flag words (256 blocks x 16 words = 4096)
    {
        int i = blockIdx.x * 16 + threadIdx.x;
        if (threadIdx.x < 16) d_flags[i] = 0;
    }
}

// ---------------------------------------------------------------------------
// Persistent recurrence + fused finalize. 148 CTAs launched; 128 work.
// 256 thr/CTA: 8 warps x 128 columns, lane l owns gate-row
//   grow = (l>>3)*HID + ct*JPC + (l&7)
// Thread k<128: acquire-spin flag[k] (its own 128B line), then load slice k.
// ---------------------------------------------------------------------------
__global__ void __launch_bounds__(NTHR, 1) tts_main(float* __restrict__ out,
                                                    const float* __restrict__ linW,
                                                    const float* __restrict__ linb,
                                                    int T, int B) {
    if (blockIdx.x >= NCTA) return;            // grid padding; dummies exit

    __shared__ float h_all[TT * HID];          // main phase uses first HID
    __shared__ float red_s[NTHR];
    __shared__ float fr[TT][MEL];
    float* h_s = h_all;

    const int tid = threadIdx.x;
    const int w   = tid >> 5;
    const int l   = tid & 31;
    const int ct  = blockIdx.x;
    const int jj  = l & 7;
    const int grow = (l >> 3) * HID + ct * JPC + jj;

    // 128-float weight slice packed as 64 f32x2 (128 regs/thread).
    unsigned long long W2[64];
    {
        const longlong2* wg =
            (const longlong2*)(d_Wcomb + (size_t)grow * HID + (w << 7));
        #pragma unroll
        for (int k = 0; k < 32; ++k) {
            longlong2 v = wg[k];
            W2[2 * k]     = (unsigned long long)v.x;
            W2[2 * k + 1] = (unsigned long long)v.y;
        }
    }
    const float bc = d_bcomb[grow];
    float c = 0.0f;

    // ---- step 0 (h = x = 0): g = b0 ----
    if (w == 0) {
        float gv = d_b0[grow];
        float vi = __shfl_sync(0xffffffffu, gv, jj);
        float vg = __shfl_sync(0xffffffffu, gv, jj + 16);
        float vo = __shfl_sync(0xffffffffu, gv, jj + 24);
        if (l < 8) {
            c = fast_sig(vi) * fast_tanh(vg);
            float hh = fast_sig(vo) * fast_tanh(c);
            asm volatile("st.global.cg.f32 [%0], %1;"
                         :: "l"(d_hhist + ct * JPC + l), "f"(hh) : "memory");
        }
        __syncwarp();
        if (l == 0)
            asm volatile("st.release.gpu.global.u32 [%0], %1;"
                         :: "l"(d_flags + ct * FPAD), "r"(1u) : "memory");
    }

    // ---- steps 1..T-1 ----
    for (int t = 1; t < T; ++t) {
        if (tid < NCTA) {
            wait_flag_acq(d_flags + tid * FPAD, (unsigned)t);
            const float4* src =
                (const float4*)(d_hhist + (size_t)(t - 1) * HID) + tid * 2;
            float4 a = __ldcg(src);
            float4 b = __ldcg(src + 1);
            ((float4*)h_s)[tid * 2]     = a;
            ((float4*)h_s)[tid * 2 + 1] = b;
        }
        __syncthreads();

        // packed 128-wide dot, h broadcast from SMEM
        unsigned long long a0 = 0ull, a1 = 0ull;
        const longlong2* h2 = (const longlong2*)(h_s + (w << 7));
        #pragma unroll
        for (int k = 0; k < 32; ++k) {
            longlong2 hv = h2[k];
            fma2(a0, W2[2 * k],     (unsigned long long)hv.x);
            fma2(a1, W2[2 * k + 1], (unsigned long long)hv.y);
        }
        float2 p0 = unpack2(a0), p1 = unpack2(a1);
        red_s[l * 8 + w] = (p0.x + p0.y) + (p1.x + p1.y);
        __syncthreads();

        if (w == 0) {
            const float4* rr = (const float4*)(red_s + l * 8);
            float4 x0 = rr[0], x1 = rr[1];
            float gv = ((x0.x + x0.y) + (x0.z + x0.w)) +
                       ((x1.x + x1.y) + (x1.z + x1.w)) + bc;
            float vi = __shfl_sync(0xffffffffu, gv, jj);
            float vf = __shfl_sync(0xffffffffu, gv, jj + 8);
            float vg = __shfl_sync(0xffffffffu, gv, jj + 16);
            float vo = __shfl_sync(0xffffffffu, gv, jj + 24);
            if (l < 8) {
                c = fast_sig(vf) * c + fast_sig(vi) * fast_tanh(vg);
                float hh = fast_sig(vo) * fast_tanh(c);
                asm volatile("st.global.cg.f32 [%0], %1;"
                             :: "l"(d_hhist + (size_t)t * HID + ct * JPC + l),
                                "f"(hh) : "memory");
            }
            __syncwarp();
            if (l == 0)
                asm volatile("st.release.gpu.global.u32 [%0], %1;"
                             :: "l"(d_flags + ct * FPAD), "r"((unsigned)(t + 1)) : "memory");
        }
    }

    // ===== full acquire barrier: all CTAs completed step T-1 =====
    if (tid < NCTA) wait_flag_acq(d_flags + tid * FPAD, (unsigned)T);
    __syncthreads();

    // ===== fused finalize: CTA ct -> timesteps [ct*TT, ct*TT+TT) =====
    const int t0 = ct * TT;
    if (t0 < T) {
        for (int i = tid; i < TT * HID / 4; i += NTHR) {
            int j = i >> 8;                 // / (HID/4)
            int k = (i & 255) << 2;
            if (t0 + j < T)
                ((float4*)(h_all + j * HID))[(j * HID + k) >> 2 & 255] =
                    __ldcg((const float4*)(d_hhist + (size_t)(t0 + j) * HID + k));
        }
        __syncthreads();

        for (int m = w; m < MEL; m += 8) {
            const float* wrow = linW + (size_t)m * HID;
            float s[TT];
            #pragma unroll
            for (int j = 0; j < TT; ++j) s[j] = 0.0f;
            for (int k = l; k < HID; k += 32) {
                float wv = wrow[k];
                #pragma unroll
                for (int j = 0; j < TT; ++j) s[j] = fmaf(wv, h_all[j * HID + k], s[j]);
            }
            #pragma unroll
            for (int j = 0; j < TT; ++j) {
                #pragma unroll
                for (int off = 16; off; off >>= 1)
                    s[j] += __shfl_down_sync(0xffffffffu, s[j], off);
            }
            if (l == 0) {
                float bb = linb[m];
                #pragma unroll
                for (int j = 0; j < TT; ++j) fr[j][m] = s[j] + bb;
            }
        }
        __syncthreads();

        const int tot = B * TT * MEL;
        for (int i = tid; i < tot; i += NTHR) {
            int b = i / (TT * MEL);
            int r = i - b * (TT * MEL);
            int j = r / MEL;
            int m = r - j * MEL;
            int t = t0 + j;
            if (t < T) out[((size_t)b * T + t) * MEL + m] = fr[j][m];
        }
    }
}

// ---------------------------------------------------------------------------
extern "C" void kernel_launch(void* const* d_in, const int* in_sizes, int n_in,
                              void* d_out, int out_size) {
    if (n_in < 6) return;
    const float* dec_Wih = (const float*)d_in[n_in - 6];
    const float* dec_Whh = (const float*)d_in[n_in - 5];
    const float* dec_bih = (const float*)d_in[n_in - 4];
    const float* dec_bhh = (const float*)d_in[n_in - 3];
    const float* lin_W   = (const float*)d_in[n_in - 2];
    const float* lin_b   = (const float*)d_in[n_in - 1];

    const int B = in_sizes[1];
    int T = out_size / (B * MEL);
    if (T > MAXT) T = MAXT;
    if (T <= 0) return;

    prep    <<<GATES / 16, 256>>>(dec_Wih, dec_Whh, lin_W, dec_bih, dec_bhh, lin_b);
    tts_main<<<GRID, NTHR>>>((float*)d_out, lin_W, lin_b, T, B);
}